// round 10
// baseline (speedup 1.0000x reference)
#include <cuda_runtime.h>
#include <cuda_bf16.h>

// PMF: out[p] = relu(dot(user_emb[user_ids[p]], item_emb[item_ids[p]])), D=64 fp32.
//
// R10: we are pinned on the chip-wide LTS wall (~11.7 TB/s at NAT): every
// structure (R4 flat registers, R7b cp.async flat, R9 cp.async pipeline) moves
// the same ~1048MB through L2 and lands at 90.6us. DRAM (5.55TB/s on random
// 256B rows) binds at the same point (traffic ratio == ceiling ratio), so
// reorder schemes that cut only one side can't win. Only lever left: cut LTS
// bytes. The 2x4B-per-warp output stores cost ~32MB of partial-sector LTS
// traffic + write-allocate fills; stage results in smem and store 512B
// contiguous per CTA (full 128B lines -> no fill, no partial sectors).
// Base structure = R4 (PB=8, 16 lanes/pair, front-batched MLP=16 loads).

#define HIDDEN 64
#define THREADS 256
#define GROUPS_PER_BLOCK (THREADS / 16)            // 16
#define PB 8                                        // pairs per group
#define PAIRS_PER_BLOCK (GROUPS_PER_BLOCK * PB)     // 128

__global__ __launch_bounds__(THREADS, 3)
void pmf_kernel(const float* __restrict__ user_emb,
                const float* __restrict__ item_emb,
                const int*   __restrict__ user_ids,
                const int*   __restrict__ item_ids,
                float*       __restrict__ out,
                int num_pairs)
{
    __shared__ float res[PAIRS_PER_BLOCK];          // 512B result staging

    const int tid   = threadIdx.x;
    const int group = tid >> 4;            // 0..15
    const int lane  = tid & 15;            // 0..15
    const int cta_base = blockIdx.x * PAIRS_PER_BLOCK;
    const int base  = cta_base + group;

    // Phase 1: all id loads, independent, front-batched.
    int uid[PB], iid[PB];
    #pragma unroll
    for (int k = 0; k < PB; k++) {
        int p = base + k * GROUPS_PER_BLOCK;
        int q = (p < num_pairs) ? p : 0;
        uid[k] = __ldg(&user_ids[q]);
        iid[k] = __ldg(&item_ids[q]);
    }

    // Phase 2: all row loads, independent, front-batched (16 LDG.128/thread).
    float4 u[PB], v[PB];
    #pragma unroll
    for (int k = 0; k < PB; k++) {
        u[k] = __ldg(reinterpret_cast<const float4*>(
                   user_emb + (long long)uid[k] * HIDDEN) + lane);
        v[k] = __ldg(reinterpret_cast<const float4*>(
                   item_emb + (long long)iid[k] * HIDDEN) + lane);
    }

    // Phase 3: dot products, 16-lane reductions, stage results in smem.
    #pragma unroll
    for (int k = 0; k < PB; k++) {
        float acc = u[k].x * v[k].x + u[k].y * v[k].y
                  + u[k].z * v[k].z + u[k].w * v[k].w;
        acc += __shfl_xor_sync(0xFFFFFFFFu, acc, 8);
        acc += __shfl_xor_sync(0xFFFFFFFFu, acc, 4);
        acc += __shfl_xor_sync(0xFFFFFFFFu, acc, 2);
        acc += __shfl_xor_sync(0xFFFFFFFFu, acc, 1);
        if (lane == 0)
            res[k * GROUPS_PER_BLOCK + group] = fmaxf(acc, 0.0f);
    }

    // Phase 4: one coalesced 512B store per CTA (full 128B sectors -> no
    // write-allocate fill, no partial-sector LTS waste).
    __syncthreads();
    if (tid < PAIRS_PER_BLOCK) {
        int p = cta_base + tid;
        if (p < num_pairs)
            out[p] = res[tid];
    }
}

extern "C" void kernel_launch(void* const* d_in, const int* in_sizes, int n_in,
                              void* d_out, int out_size)
{
    const float* user_emb = (const float*)d_in[0];
    const float* item_emb = (const float*)d_in[1];
    const int*   user_ids = (const int*)d_in[2];
    const int*   item_ids = (const int*)d_in[3];
    float*       out      = (float*)d_out;

    int num_pairs = in_sizes[2];
    int blocks = (num_pairs + PAIRS_PER_BLOCK - 1) / PAIRS_PER_BLOCK;

    pmf_kernel<<<blocks, THREADS>>>(user_emb, item_emb, user_ids, item_ids,
                                    out, num_pairs);
}

// round 11
// speedup vs baseline: 1.0233x; 1.0233x over previous
#include <cuda_runtime.h>
#include <cuda_bf16.h>

// PMF: out[p] = relu(dot(user_emb[user_ids[p]], item_emb[item_ids[p]])), D=64 fp32.
//
// R11: final wall-riding kernel. Five structurally different kernels (register
// MLP, cp.async flat, cp.async 3-stage pipeline, smem-staged stores, reorder
// pipelines) all converge to ~90us because the direct gather's L2 (LTS)
// traffic is invariant at ~1048MB and the chip-wide LTS cap (~6300 B/cyc ~=
// 11.7TB/s @NAT) gives a 89.6us floor; DRAM binds at the same point.
// Structure = R4 (best, reproduced twice): 16 lanes/pair, PB=8 pairs/group,
// all 16 ids then all 16 float4 row loads front-batched (MLP=16/thread),
// 16-lane shfl reduce, direct store.
// Only change: ids are read with __ldcs and ratings written with __stcs
// (evict-first) so single-use streams don't displace item rows / user-repeat
// lines in L2.

#define HIDDEN 64
#define THREADS 256
#define GROUPS_PER_BLOCK (THREADS / 16)            // 16
#define PB 8                                        // pairs per group
#define PAIRS_PER_BLOCK (GROUPS_PER_BLOCK * PB)     // 128

__global__ __launch_bounds__(THREADS, 3)
void pmf_kernel(const float* __restrict__ user_emb,
                const float* __restrict__ item_emb,
                const int*   __restrict__ user_ids,
                const int*   __restrict__ item_ids,
                float*       __restrict__ out,
                int num_pairs)
{
    const int group = threadIdx.x >> 4;    // 0..15
    const int lane  = threadIdx.x & 15;    // 0..15
    const int base  = blockIdx.x * PAIRS_PER_BLOCK + group;

    // Phase 1: all id loads, independent, front-batched. Streaming (evict-
    // first): ids are single-use, keep them out of L2's useful capacity.
    int uid[PB], iid[PB];
    #pragma unroll
    for (int k = 0; k < PB; k++) {
        int p = base + k * GROUPS_PER_BLOCK;
        int q = (p < num_pairs) ? p : 0;
        uid[k] = __ldcs(&user_ids[q]);
        iid[k] = __ldcs(&item_ids[q]);
    }

    // Phase 2: all row loads, independent, front-batched (16 LDG.128/thread).
    float4 u[PB], v[PB];
    #pragma unroll
    for (int k = 0; k < PB; k++) {
        u[k] = __ldg(reinterpret_cast<const float4*>(
                   user_emb + (long long)uid[k] * HIDDEN) + lane);
        v[k] = __ldg(reinterpret_cast<const float4*>(
                   item_emb + (long long)iid[k] * HIDDEN) + lane);
    }

    // Phase 3: dot products, 16-lane reductions, streaming stores.
    #pragma unroll
    for (int k = 0; k < PB; k++) {
        float acc = u[k].x * v[k].x + u[k].y * v[k].y
                  + u[k].z * v[k].z + u[k].w * v[k].w;
        acc += __shfl_xor_sync(0xFFFFFFFFu, acc, 8);
        acc += __shfl_xor_sync(0xFFFFFFFFu, acc, 4);
        acc += __shfl_xor_sync(0xFFFFFFFFu, acc, 2);
        acc += __shfl_xor_sync(0xFFFFFFFFu, acc, 1);
        int p = base + k * GROUPS_PER_BLOCK;
        if (lane == 0 && p < num_pairs)
            __stcs(&out[p], fmaxf(acc, 0.0f));
    }
}

extern "C" void kernel_launch(void* const* d_in, const int* in_sizes, int n_in,
                              void* d_out, int out_size)
{
    const float* user_emb = (const float*)d_in[0];
    const float* item_emb = (const float*)d_in[1];
    const int*   user_ids = (const int*)d_in[2];
    const int*   item_ids = (const int*)d_in[3];
    float*       out      = (float*)d_out;

    int num_pairs = in_sizes[2];
    int blocks = (num_pairs + PAIRS_PER_BLOCK - 1) / PAIRS_PER_BLOCK;

    pmf_kernel<<<blocks, THREADS>>>(user_emb, item_emb, user_ids, item_ids,
                                    out, num_pairs);
}